// round 13
// baseline (speedup 1.0000x reference)
#include <cuda_runtime.h>
#include <cuda_fp16.h>
#include <math.h>
#include <stdint.h>

#define N_NODES 50000
#define N_EDGES 800000
#define H 128
#define LN_EPS 1e-5f

// fp16 (HMMA) tile layouts — unchanged from R11
#define AS3_STRIDE 36    // uint2 units per A row (32 data + 4 pad)
#define BS3_STRIDE 132   // uint2 units per B pair-row (128 data + 4 pad)
#define CS_STRIDE  132   // float units per C row in epilogue staging
#define SMEM_A3 (64 * AS3_STRIDE * 8)            // 18432 B
#define SMEM_B3 (32 * BS3_STRIDE * 8)            // 33792 B
#define SMEM_TILE (SMEM_A3 + SMEM_B3)            // 52224 B (fp32 path needs 49152)

// Static device scratch
__device__ uint32_t g_PQh[(size_t)N_NODES * 128];   // P|Q fp16 pairs per node
__device__ uint2    g_Wh[3 * 32 * BS3_STRIDE];      // W pre-packed fp16 k-paired

// ---------------- helpers ----------------
__device__ __forceinline__ uint32_t pack_h2(float a, float b) {
    uint32_t u;
    asm("cvt.rn.f16x2.f32 %0, %1, %2;" : "=r"(u) : "f"(b), "f"(a));
    return u;
}

__device__ __forceinline__ float2 h2f2(uint32_t u) {
    __half2 h = *(__half2*)&u;
    return __half22float2(h);
}

__device__ __forceinline__ void mma_f16(float d[4], uint32_t a0, uint32_t a1,
                                        uint32_t a2, uint32_t a3,
                                        uint32_t b0, uint32_t b1) {
    asm volatile(
        "mma.sync.aligned.m16n8k16.row.col.f32.f16.f16.f32 "
        "{%0,%1,%2,%3}, {%4,%5,%6,%7}, {%8,%9}, {%0,%1,%2,%3};"
        : "+f"(d[0]), "+f"(d[1]), "+f"(d[2]), "+f"(d[3])
        : "r"(a0), "r"(a1), "r"(a2), "r"(a3), "r"(b0), "r"(b1));
}

// packed f32x2 (FFMA2) helpers
__device__ __forceinline__ unsigned long long pack_f2(float lo, float hi) {
    unsigned long long u;
    asm("mov.b64 %0, {%1, %2};" : "=l"(u) : "f"(lo), "f"(hi));
    return u;
}
__device__ __forceinline__ unsigned long long fma2(unsigned long long a,
                                                   unsigned long long b,
                                                   unsigned long long c) {
    unsigned long long d;
    asm("fma.rn.f32x2 %0, %1, %2, %3;" : "=l"(d) : "l"(a), "l"(b), "l"(c));
    return d;
}
__device__ __forceinline__ float2 unpack_f2(unsigned long long u) {
    float2 v;
    asm("mov.b64 {%0, %1}, %2;" : "=f"(v.x), "=f"(v.y) : "l"(u));
    return v;
}

// ---------------------------------------------------------------------------
// Kernel 0: pack W1 sections into fp16 k-paired layout (all 3 sections).
// ---------------------------------------------------------------------------
__global__ __launch_bounds__(256) void pack_w_kernel(const float* __restrict__ W1) {
    const int tid = threadIdx.x;
    for (int sec = 0; sec < 3; ++sec) {
        const float* B = W1 + (size_t)sec * 128 * H;
        uint2* W = g_Wh + sec * 32 * BS3_STRIDE;
#pragma unroll
        for (int it = 0; it < 4; ++it) {
            int idx = tid + it * 256;
            int pr  = idx >> 5;
            int ng  = idx & 31;
            int kp  = ((pr >> 2) << 3) + (pr & 3);
            float4 v0 = *(const float4*)(B + (size_t)(2 * kp)     * H + ng * 4);
            float4 v1 = *(const float4*)(B + (size_t)(2 * kp + 1) * H + ng * 4);
            float4 v2 = *(const float4*)(B + (size_t)(2 * kp + 8) * H + ng * 4);
            float4 v3 = *(const float4*)(B + (size_t)(2 * kp + 9) * H + ng * 4);
            uint2* dst = W + pr * BS3_STRIDE + ng * 4;
            dst[0] = make_uint2(pack_h2(v0.x, v1.x), pack_h2(v2.x, v3.x));
            dst[1] = make_uint2(pack_h2(v0.y, v1.y), pack_h2(v2.y, v3.y));
            dst[2] = make_uint2(pack_h2(v0.z, v1.z), pack_h2(v2.z, v3.z));
            dst[3] = make_uint2(pack_h2(v0.w, v1.w), pack_h2(v2.w, v3.w));
        }
    }
}

// ---------------------------------------------------------------------------
// fp16 HMMA mainloop (unchanged from R11)
// ---------------------------------------------------------------------------
__device__ __forceinline__ void run_mainloop(const uint2* __restrict__ As3,
                                             const uint2* __restrict__ Bs3,
                                             int m_base, int n_base, int g, int tig,
                                             float d[8][4]) {
#pragma unroll
    for (int ks = 0; ks < 8; ++ks) {
        const uint2* ar = As3 + (m_base + g) * AS3_STRIDE + ks * 4 + tig;
        uint2 alo = ar[0];
        uint2 ahi = ar[8 * AS3_STRIDE];
        const uint2* br = Bs3 + (ks * 4 + tig) * BS3_STRIDE + n_base + g;
#pragma unroll
        for (int j = 0; j < 8; ++j) {
            uint2 b = br[j * 8];
            mma_f16(d[j], alo.x, ahi.x, alo.y, ahi.y, b.x, b.y);
        }
    }
}

// Shared epilogue: msg = relu(Cs + P[s] + Q[r]); red.v4 scatter into out[r]
__device__ __forceinline__ void edge_epilogue(const float* __restrict__ Cs, int e0,
                                              const int* __restrict__ senders,
                                              const int* __restrict__ receivers,
                                              float* __restrict__ out, int tid) {
    const int eg = tid >> 5;
    const int og = tid & 31;
#pragma unroll
    for (int i = 0; i < 8; ++i) {
        int el = eg * 8 + i;
        int e  = e0 + el;
        int s  = senders[e];
        int r  = receivers[e];
        float4 m = *(const float4*)(Cs + el * CS_STRIDE + og * 4);
        uint2 pu = *(const uint2*)(g_PQh + (size_t)s * 128 + og * 2);
        uint2 qu = *(const uint2*)(g_PQh + (size_t)r * 128 + 64 + og * 2);
        float2 p0 = h2f2(pu.x), p1 = h2f2(pu.y);
        float2 q0 = h2f2(qu.x), q1 = h2f2(qu.y);
        m.x = fmaxf(m.x + p0.x + q0.x, 0.f);
        m.y = fmaxf(m.y + p0.y + q0.y, 0.f);
        m.z = fmaxf(m.z + p1.x + q1.x, 0.f);
        m.w = fmaxf(m.w + p1.y + q1.y, 0.f);
        float* dst = out + (size_t)r * H + og * 4;
        asm volatile("red.global.add.v4.f32 [%0], {%1,%2,%3,%4};"
                     :: "l"(dst), "f"(m.x), "f"(m.y), "f"(m.z), "f"(m.w)
                     : "memory");
    }
}

// ---------------------------------------------------------------------------
// Kernel 1: node projection (fp16 mma, unchanged from R11).
// ---------------------------------------------------------------------------
__global__ __launch_bounds__(256) void proj_kernel(const float* __restrict__ x,
                                                   const float* __restrict__ b1,
                                                   float* __restrict__ out) {
    extern __shared__ float smem_dyn[];
    uint2* As3 = (uint2*)smem_dyn;
    uint2* Bs3 = (uint2*)smem_dyn + 64 * AS3_STRIDE;

    const int tid  = threadIdx.x;
    const int half = blockIdx.y;
    const int m0   = blockIdx.x * 64;

    const uint2* W = g_Wh + half * 32 * BS3_STRIDE;
#pragma unroll
    for (int it = 0; it < 8; ++it) {
        int idx = tid + it * 256;
        int pr  = idx >> 6;
        int n2  = idx & 63;
        uint4 v = *(const uint4*)(W + pr * BS3_STRIDE + n2 * 2);
        *(uint4*)(Bs3 + pr * BS3_STRIDE + n2 * 2) = v;
    }

#pragma unroll
    for (int it = 0; it < 4; ++it) {
        int idx = tid + it * 256;
        int m   = idx >> 4;
        int r   = idx & 15;
        int ks  = r >> 1;
        int c   = r & 1;
        int n   = m0 + m;
        float4 vlo = make_float4(0.f, 0.f, 0.f, 0.f);
        float4 vhi = vlo;
        if (n < N_NODES) {
            const float* src = x + (size_t)n * H + (4 * ks + c) * 4;
            vlo = *(const float4*)(src);
            vhi = *(const float4*)(src + 8);
            if (half == 0) {
                float* o = out + (size_t)n * H + (4 * ks + c) * 4;
                *(float4*)(o)     = vlo;
                *(float4*)(o + 8) = vhi;
            }
        }
        uint2* dst = As3 + m * AS3_STRIDE + 4 * ks + 2 * c;
        dst[0] = make_uint2(pack_h2(vlo.x, vlo.y), pack_h2(vhi.x, vhi.y));
        dst[1] = make_uint2(pack_h2(vlo.z, vlo.w), pack_h2(vhi.z, vhi.w));
    }
    __syncthreads();

    const int lane = tid & 31;
    const int wid  = tid >> 5;
    const int g    = lane >> 2;
    const int tig  = lane & 3;
    const int m_base = (wid & 3) * 16;
    const int n_base = (wid >> 2) * 64;

    float d[8][4];
#pragma unroll
    for (int j = 0; j < 8; ++j)
#pragma unroll
        for (int i = 0; i < 4; ++i) d[j][i] = 0.f;

    run_mainloop(As3, Bs3, m_base, n_base, g, tig, d);
    __syncthreads();

    float* Cs = smem_dyn;
#pragma unroll
    for (int j = 0; j < 8; ++j) {
        int c = n_base + j * 8 + 2 * tig;
        *(float2*)(Cs + (m_base + g) * CS_STRIDE + c)     = make_float2(d[j][0], d[j][1]);
        *(float2*)(Cs + (m_base + g + 8) * CS_STRIDE + c) = make_float2(d[j][2], d[j][3]);
    }
    __syncthreads();

    const int eg = tid >> 5;
    const int og = tid & 31;
    float4 bias = make_float4(0.f, 0.f, 0.f, 0.f);
    if (half == 0) bias = *(const float4*)(b1 + og * 4);

#pragma unroll
    for (int i = 0; i < 8; ++i) {
        int el = eg * 8 + i;
        int n  = m0 + el;
        if (n < N_NODES) {
            float4 v = *(const float4*)(Cs + el * CS_STRIDE + og * 4);
            v.x += bias.x; v.y += bias.y; v.z += bias.z; v.w += bias.w;
            uint2 u;
            u.x = pack_h2(v.x, v.y);
            u.y = pack_h2(v.z, v.w);
            *(uint2*)(g_PQh + (size_t)n * 128 + half * 64 + og * 2) = u;
        }
    }
}

// ---------------------------------------------------------------------------
// Kernel 2: edge GEMM — heterogeneous: 4/5 of tiles on fp16 HMMA (tensor pipe),
// 1/5 on fp32 FFMA2 (fma pipe). Both pipes busy concurrently per SM.
// ---------------------------------------------------------------------------
__global__ __launch_bounds__(256) void edge_kernel(const float* __restrict__ ef,
                                                   const int* __restrict__ senders,
                                                   const int* __restrict__ receivers,
                                                   const float* __restrict__ W1,
                                                   float* __restrict__ out) {
    extern __shared__ float smem_dyn[];
    const int tid = threadIdx.x;
    const int e0  = blockIdx.x * 64;
    const int eg  = tid >> 5;
    const int og  = tid & 31;

    if ((blockIdx.x % 5) != 4) {
        // ---------------- fp16 HMMA path (R11) ----------------
        uint2* As3 = (uint2*)smem_dyn;
        uint2* Bs3 = (uint2*)smem_dyn + 64 * AS3_STRIDE;

        const uint2* W = g_Wh + 2 * 32 * BS3_STRIDE;
#pragma unroll
        for (int it = 0; it < 8; ++it) {
            int idx = tid + it * 256;
            int pr  = idx >> 6;
            int n2  = idx & 63;
            uint4 v = *(const uint4*)(W + pr * BS3_STRIDE + n2 * 2);
            *(uint4*)(Bs3 + pr * BS3_STRIDE + n2 * 2) = v;
        }

#pragma unroll
        for (int it = 0; it < 4; ++it) {
            int idx = tid + it * 256;
            int e   = idx >> 4;
            int r   = idx & 15;
            int ks  = r >> 1;
            int c   = r & 1;
            const float* src = ef + (size_t)(e0 + e) * H + (4 * ks + c) * 4;
            float4 vlo = *(const float4*)(src);
            float4 vhi = *(const float4*)(src + 8);
            uint2* dst = As3 + e * AS3_STRIDE + 4 * ks + 2 * c;
            dst[0] = make_uint2(pack_h2(vlo.x, vlo.y), pack_h2(vhi.x, vhi.y));
            dst[1] = make_uint2(pack_h2(vlo.z, vlo.w), pack_h2(vhi.z, vhi.w));
        }
        __syncthreads();

        const int lane = tid & 31;
        const int wid  = tid >> 5;
        const int g    = lane >> 2;
        const int tig  = lane & 3;
        const int m_base = (wid & 3) * 16;
        const int n_base = (wid >> 2) * 64;

        float d[8][4];
#pragma unroll
        for (int j = 0; j < 8; ++j)
#pragma unroll
            for (int i = 0; i < 4; ++i) d[j][i] = 0.f;

        run_mainloop(As3, Bs3, m_base, n_base, g, tig, d);
        __syncthreads();

        float* Cs = smem_dyn;
#pragma unroll
        for (int j = 0; j < 8; ++j) {
            int c = n_base + j * 8 + 2 * tig;
            *(float2*)(Cs + (m_base + g) * CS_STRIDE + c)     = make_float2(d[j][0], d[j][1]);
            *(float2*)(Cs + (m_base + g + 8) * CS_STRIDE + c) = make_float2(d[j][2], d[j][3]);
        }
        __syncthreads();

        edge_epilogue(Cs, e0, senders, receivers, out, tid);
    } else {
        // ---------------- fp32 FFMA2 path (fma pipe) ----------------
        float* Asf = smem_dyn;               // [128][64] transposed A
        float* Bsf = smem_dyn + 128 * 64;    // [32][128] staged W chunk

        // A tile transposed: thread -> (edge, k-group)
#pragma unroll
        for (int it = 0; it < 8; ++it) {
            int idx = tid + it * 256;
            int e   = idx & 63;
            int kg  = idx >> 6;
            float4 v = *(const float4*)(ef + (size_t)(e0 + e) * H + kg * 4);
            Asf[(kg * 4 + 0) * 64 + e] = v.x;
            Asf[(kg * 4 + 1) * 64 + e] = v.y;
            Asf[(kg * 4 + 2) * 64 + e] = v.z;
            Asf[(kg * 4 + 3) * 64 + e] = v.w;
        }

        unsigned long long acc2[8][2];
#pragma unroll
        for (int i = 0; i < 8; ++i) {
            acc2[i][0] = pack_f2(0.f, 0.f);
            acc2[i][1] = pack_f2(0.f, 0.f);
        }

        const float* B = W1 + (size_t)256 * H;   // We fp32
        for (int kc = 0; kc < 4; ++kc) {
            __syncthreads();
#pragma unroll
            for (int it = 0; it < 4; ++it) {
                int idx = tid + it * 256;
                int o4  = idx & 31;
                int r   = idx >> 5;
                *(float4*)(Bsf + r * 128 + o4 * 4) =
                    *(const float4*)(B + (size_t)(kc * 32 + r) * H + o4 * 4);
            }
            __syncthreads();
#pragma unroll
            for (int k = 0; k < 32; ++k) {
                const float* ap = Asf + (kc * 32 + k) * 64 + eg * 8;
                float4 a0 = *(const float4*)(ap);
                float4 a1 = *(const float4*)(ap + 4);
                float4 b  = *(const float4*)(Bsf + k * 128 + og * 4);
                unsigned long long b01 = pack_f2(b.x, b.y);
                unsigned long long b23 = pack_f2(b.z, b.w);
                float ar[8] = {a0.x, a0.y, a0.z, a0.w, a1.x, a1.y, a1.z, a1.w};
#pragma unroll
                for (int i = 0; i < 8; ++i) {
                    unsigned long long ai = pack_f2(ar[i], ar[i]);
                    acc2[i][0] = fma2(ai, b01, acc2[i][0]);
                    acc2[i][1] = fma2(ai, b23, acc2[i][1]);
                }
            }
        }
        __syncthreads();

        float* Cs = smem_dyn;
#pragma unroll
        for (int i = 0; i < 8; ++i) {
            float2 lo = unpack_f2(acc2[i][0]);
            float2 hi = unpack_f2(acc2[i][1]);
            float* dst = Cs + (eg * 8 + i) * CS_STRIDE + og * 4;
            dst[0] = lo.x; dst[1] = lo.y; dst[2] = hi.x; dst[3] = hi.y;
        }
        __syncthreads();

        edge_epilogue(Cs, e0, senders, receivers, out, tid);
    }
}

// ---------------------------------------------------------------------------
// Kernel 3: in-place LayerNorm, one warp per row
// ---------------------------------------------------------------------------
__global__ __launch_bounds__(256) void ln_kernel(float* __restrict__ out,
                                                 const float* __restrict__ gamma,
                                                 const float* __restrict__ beta) {
    int warp = threadIdx.x >> 5;
    int lane = threadIdx.x & 31;
    int row  = blockIdx.x * 8 + warp;
    if (row >= N_NODES) return;

    float4 h = *(const float4*)(out + (size_t)row * H + lane * 4);
    float s  = h.x + h.y + h.z + h.w;
    float s2 = h.x * h.x + h.y * h.y + h.z * h.z + h.w * h.w;
#pragma unroll
    for (int off = 16; off > 0; off >>= 1) {
        s  += __shfl_xor_sync(0xffffffffu, s, off);
        s2 += __shfl_xor_sync(0xffffffffu, s2, off);
    }
    float mean = s * (1.f / H);
    float var  = s2 * (1.f / H) - mean * mean;
    float rstd = rsqrtf(var + LN_EPS);

    float4 g = *(const float4*)(gamma + lane * 4);
    float4 b = *(const float4*)(beta + lane * 4);
    float4 o;
    o.x = g.x * (h.x - mean) * rstd + b.x;
    o.y = g.y * (h.y - mean) * rstd + b.y;
    o.z = g.z * (h.z - mean) * rstd + b.z;
    o.w = g.w * (h.w - mean) * rstd + b.w;
    *(float4*)(out + (size_t)row * H + lane * 4) = o;
}

// ---------------------------------------------------------------------------
extern "C" void kernel_launch(void* const* d_in, const int* in_sizes, int n_in,
                              void* d_out, int out_size) {
    const float* x         = (const float*)d_in[0];
    const int*   senders   = (const int*)d_in[1];
    const int*   receivers = (const int*)d_in[2];
    const float* ef        = (const float*)d_in[3];
    const float* W1        = (const float*)d_in[4];
    const float* b1        = (const float*)d_in[5];
    const float* gamma     = (const float*)d_in[6];
    const float* beta      = (const float*)d_in[7];
    float*       out       = (float*)d_out;

    cudaFuncSetAttribute(edge_kernel, cudaFuncAttributeMaxDynamicSharedMemorySize,
                         SMEM_TILE);
    cudaFuncSetAttribute(proj_kernel, cudaFuncAttributeMaxDynamicSharedMemorySize,
                         SMEM_TILE);

    pack_w_kernel<<<1, 256>>>(W1);
    proj_kernel<<<dim3((N_NODES + 63) / 64, 2), 256, SMEM_TILE>>>(x, b1, out);
    edge_kernel<<<N_EDGES / 64, 256, SMEM_TILE>>>(ef, senders, receivers, W1, out);
    ln_kernel<<<N_NODES / 8, 256>>>(out, gamma, beta);
}

// round 14
// speedup vs baseline: 1.3692x; 1.3692x over previous
#include <cuda_runtime.h>
#include <cuda_fp16.h>
#include <math.h>
#include <stdint.h>

#define N_NODES 50000
#define N_EDGES 800000
#define H 128
#define LN_EPS 1e-5f

// k-paired layouts: element = uint2 { f16x2(k-pair kp) , f16x2(k-pair kp+4) }
// A: 64 rows x 32 pairs, stride 36 uint2 (conflict-free LDS.64)
// B: 32 pair-rows x 128 cols, stride 132 uint2 (conflict-free LDS.64)
#define AS3_STRIDE 36    // uint2 units per A row (32 data + 4 pad)
#define BS3_STRIDE 132   // uint2 units per B pair-row (128 data + 4 pad)
#define CS_STRIDE  132   // float units per C row in epilogue staging
#define SMEM_A3 (64 * AS3_STRIDE * 8)            // 18432 B
#define SMEM_B3 (32 * BS3_STRIDE * 8)            // 33792 B
#define SMEM_TILE (SMEM_A3 + SMEM_B3)            // 52224 B (4 CTA/SM)

// Static device scratch
// g_PQh: per-node projections, fp16 half2 pairs. [node][128] uint32:
//   0..63 = P = x@Ws + b1, 64..127 = Q = x@Wr
__device__ uint32_t g_PQh[(size_t)N_NODES * 128];
// g_Wh: W1 pre-packed fp16 k-PAIRED tiles: [3][32*BS3_STRIDE] uint2 (Ws|Wr|We)
__device__ uint2 g_Wh[3 * 32 * BS3_STRIDE];

// Pack two floats into f16x2: lo half = a, hi half = b.
__device__ __forceinline__ uint32_t pack_h2(float a, float b) {
    uint32_t u;
    asm("cvt.rn.f16x2.f32 %0, %1, %2;" : "=r"(u) : "f"(b), "f"(a));
    return u;
}

__device__ __forceinline__ float2 h2f2(uint32_t u) {
    __half2 h = *(__half2*)&u;
    return __half22float2(h);
}

__device__ __forceinline__ uint32_t smem_u32(const void* p) {
    uint32_t a;
    asm("{ .reg .u64 t; cvta.to.shared.u64 t, %1; cvt.u32.u64 %0, t; }" : "=r"(a) : "l"(p));
    return a;
}

__device__ __forceinline__ void cp_async16(uint32_t dst_smem, const void* src) {
    asm volatile("cp.async.cg.shared.global [%0], [%1], 16;"
                 :: "r"(dst_smem), "l"(src) : "memory");
}

__device__ __forceinline__ void cp_async_commit_wait() {
    asm volatile("cp.async.commit_group;" ::: "memory");
    asm volatile("cp.async.wait_group 0;" ::: "memory");
}

__device__ __forceinline__ void mma_f16(float d[4], uint32_t a0, uint32_t a1,
                                        uint32_t a2, uint32_t a3,
                                        uint32_t b0, uint32_t b1) {
    asm volatile(
        "mma.sync.aligned.m16n8k16.row.col.f32.f16.f16.f32 "
        "{%0,%1,%2,%3}, {%4,%5,%6,%7}, {%8,%9}, {%0,%1,%2,%3};"
        : "+f"(d[0]), "+f"(d[1]), "+f"(d[2]), "+f"(d[3])
        : "r"(a0), "r"(a1), "r"(a2), "r"(a3), "r"(b0), "r"(b1));
}

// ---------------------------------------------------------------------------
// Kernel 0: pack W1 sections into fp16 k-PAIRED layout.
// pair-row pr <-> (kp, kp+4) with kp = (pr>>2)*8 + (pr&3).
// Bs3[pr][n] = { h2(W[2kp][n],W[2kp+1][n]), h2(W[2kp+8][n],W[2kp+9][n]) }
// ---------------------------------------------------------------------------
__global__ __launch_bounds__(256) void pack_w_kernel(const float* __restrict__ W1) {
    const int tid = threadIdx.x;
    for (int sec = 0; sec < 3; ++sec) {
        const float* B = W1 + (size_t)sec * 128 * H;
        uint2* W = g_Wh + sec * 32 * BS3_STRIDE;
#pragma unroll
        for (int it = 0; it < 4; ++it) {
            int idx = tid + it * 256;        // 0..1023
            int pr  = idx >> 5;              // 0..31
            int ng  = idx & 31;              // n = 4*ng..+3
            int kp  = ((pr >> 2) << 3) + (pr & 3);
            float4 v0 = *(const float4*)(B + (size_t)(2 * kp)     * H + ng * 4);
            float4 v1 = *(const float4*)(B + (size_t)(2 * kp + 1) * H + ng * 4);
            float4 v2 = *(const float4*)(B + (size_t)(2 * kp + 8) * H + ng * 4);
            float4 v3 = *(const float4*)(B + (size_t)(2 * kp + 9) * H + ng * 4);
            uint2* dst = W + pr * BS3_STRIDE + ng * 4;
            dst[0] = make_uint2(pack_h2(v0.x, v1.x), pack_h2(v2.x, v3.x));
            dst[1] = make_uint2(pack_h2(v0.y, v1.y), pack_h2(v2.y, v3.y));
            dst[2] = make_uint2(pack_h2(v0.z, v1.z), pack_h2(v2.z, v3.z));
            dst[3] = make_uint2(pack_h2(v0.w, v1.w), pack_h2(v2.w, v3.w));
        }
    }
}

// ---------------------------------------------------------------------------
// Shared mainloop: A (paired) x B (paired) -> d[8][4], LDS.64 fragments
// ---------------------------------------------------------------------------
__device__ __forceinline__ void run_mainloop(const uint2* __restrict__ As3,
                                             const uint2* __restrict__ Bs3,
                                             int m_base, int n_base, int g, int tig,
                                             float d[8][4]) {
#pragma unroll
    for (int ks = 0; ks < 8; ++ks) {
        const uint2* ar = As3 + (m_base + g) * AS3_STRIDE + ks * 4 + tig;
        uint2 alo = ar[0];                    // {row g:   kp0+tig, kp0+tig+4}
        uint2 ahi = ar[8 * AS3_STRIDE];       // {row g+8: same pair}
        const uint2* br = Bs3 + (ks * 4 + tig) * BS3_STRIDE + n_base + g;
#pragma unroll
        for (int j = 0; j < 8; ++j) {
            uint2 b = br[j * 8];              // {row kp0+tig, row kp0+tig+4}
            mma_f16(d[j], alo.x, ahi.x, alo.y, ahi.y, b.x, b.y);
        }
    }
}

// ---------------------------------------------------------------------------
// Kernel 1: node projection on fp16 tensor cores.
// blockIdx.y = 0: P = x@Ws + b1, also out = x (residual preload).
// blockIdx.y = 1: Q = x@Wr.  Output packed fp16 into g_PQh.
// ---------------------------------------------------------------------------
__global__ __launch_bounds__(256) void proj_kernel(const float* __restrict__ x,
                                                   const float* __restrict__ b1,
                                                   float* __restrict__ out) {
    extern __shared__ float smem_dyn[];
    uint2* As3 = (uint2*)smem_dyn;
    uint2* Bs3 = (uint2*)smem_dyn + 64 * AS3_STRIDE;

    const int tid  = threadIdx.x;
    const int half = blockIdx.y;
    const int m0   = blockIdx.x * 64;

    // B tile: async 16B copy of pre-packed section (overlaps A-load below)
    const uint2* W = g_Wh + half * 32 * BS3_STRIDE;
#pragma unroll
    for (int it = 0; it < 8; ++it) {
        int idx = tid + it * 256;            // 0..2047
        int pr  = idx >> 6;                  // 0..31
        int n2  = idx & 63;                  // uint4 index
        cp_async16(smem_u32(Bs3 + pr * BS3_STRIDE + n2 * 2),
                   W + pr * BS3_STRIDE + n2 * 2);
    }

    // A tile: x rows -> paired fp16; half 0 also preloads out = x
#pragma unroll
    for (int it = 0; it < 4; ++it) {
        int idx = tid + it * 256;            // 0..1023
        int m   = idx >> 4;                  // 0..63
        int r   = idx & 15;
        int ks  = r >> 1;
        int c   = r & 1;
        int n   = m0 + m;
        float4 vlo = make_float4(0.f, 0.f, 0.f, 0.f);
        float4 vhi = vlo;
        if (n < N_NODES) {
            const float* src = x + (size_t)n * H + (4 * ks + c) * 4;
            vlo = *(const float4*)(src);
            vhi = *(const float4*)(src + 8);
            if (half == 0) {
                float* o = out + (size_t)n * H + (4 * ks + c) * 4;
                *(float4*)(o)     = vlo;
                *(float4*)(o + 8) = vhi;
            }
        }
        uint2* dst = As3 + m * AS3_STRIDE + 4 * ks + 2 * c;
        dst[0] = make_uint2(pack_h2(vlo.x, vlo.y), pack_h2(vhi.x, vhi.y));
        dst[1] = make_uint2(pack_h2(vlo.z, vlo.w), pack_h2(vhi.z, vhi.w));
    }
    cp_async_commit_wait();
    __syncthreads();

    const int lane = tid & 31;
    const int wid  = tid >> 5;
    const int g    = lane >> 2;
    const int tig  = lane & 3;
    const int m_base = (wid & 3) * 16;
    const int n_base = (wid >> 2) * 64;

    float d[8][4];
#pragma unroll
    for (int j = 0; j < 8; ++j)
#pragma unroll
        for (int i = 0; i < 4; ++i) d[j][i] = 0.f;

    run_mainloop(As3, Bs3, m_base, n_base, g, tig, d);
    __syncthreads();

    float* Cs = smem_dyn;   // overlaps A+B start — safe, B no longer needed
#pragma unroll
    for (int j = 0; j < 8; ++j) {
        int c = n_base + j * 8 + 2 * tig;
        *(float2*)(Cs + (m_base + g) * CS_STRIDE + c)     = make_float2(d[j][0], d[j][1]);
        *(float2*)(Cs + (m_base + g + 8) * CS_STRIDE + c) = make_float2(d[j][2], d[j][3]);
    }
    __syncthreads();

    const int eg = tid >> 5;
    const int og = tid & 31;
    float4 bias = make_float4(0.f, 0.f, 0.f, 0.f);
    if (half == 0) bias = *(const float4*)(b1 + og * 4);

#pragma unroll
    for (int i = 0; i < 8; ++i) {
        int el = eg * 8 + i;
        int n  = m0 + el;
        if (n < N_NODES) {
            float4 v = *(const float4*)(Cs + el * CS_STRIDE + og * 4);
            v.x += bias.x; v.y += bias.y; v.z += bias.z; v.w += bias.w;
            uint2 u;
            u.x = pack_h2(v.x, v.y);
            u.y = pack_h2(v.z, v.w);
            *(uint2*)(g_PQh + (size_t)n * 128 + half * 64 + og * 2) = u;
        }
    }
}

// ---------------------------------------------------------------------------
// Kernel 2: edge GEMM (single 64-edge tile per block, R11 structure,
// B-tile copy via cp.async overlapping the A-tile load+convert).
// ---------------------------------------------------------------------------
__global__ __launch_bounds__(256) void edge_kernel(const float* __restrict__ ef,
                                                   const int* __restrict__ senders,
                                                   const int* __restrict__ receivers,
                                                   float* __restrict__ out) {
    extern __shared__ float smem_dyn[];
    uint2* As3 = (uint2*)smem_dyn;
    uint2* Bs3 = (uint2*)smem_dyn + 64 * AS3_STRIDE;

    const int tid = threadIdx.x;
    const int e0  = blockIdx.x * 64;

    // B tile: async 16B copy of pre-packed We (section 2)
    const uint2* W = g_Wh + 2 * 32 * BS3_STRIDE;
#pragma unroll
    for (int it = 0; it < 8; ++it) {
        int idx = tid + it * 256;
        int pr  = idx >> 6;
        int n2  = idx & 63;
        cp_async16(smem_u32(Bs3 + pr * BS3_STRIDE + n2 * 2),
                   W + pr * BS3_STRIDE + n2 * 2);
    }

    // A tile: edge_feat rows -> paired fp16 (overlaps the async B copy)
#pragma unroll
    for (int it = 0; it < 4; ++it) {
        int idx = tid + it * 256;
        int e   = idx >> 4;
        int r   = idx & 15;
        int ks  = r >> 1;
        int c   = r & 1;
        const float* src = ef + (size_t)(e0 + e) * H + (4 * ks + c) * 4;
        float4 vlo = *(const float4*)(src);
        float4 vhi = *(const float4*)(src + 8);
        uint2* dst = As3 + e * AS3_STRIDE + 4 * ks + 2 * c;
        dst[0] = make_uint2(pack_h2(vlo.x, vlo.y), pack_h2(vhi.x, vhi.y));
        dst[1] = make_uint2(pack_h2(vlo.z, vlo.w), pack_h2(vhi.z, vhi.w));
    }
    cp_async_commit_wait();
    __syncthreads();

    const int lane = tid & 31;
    const int wid  = tid >> 5;
    const int g    = lane >> 2;
    const int tig  = lane & 3;
    const int m_base = (wid & 3) * 16;
    const int n_base = (wid >> 2) * 64;

    float d[8][4];
#pragma unroll
    for (int j = 0; j < 8; ++j)
#pragma unroll
        for (int i = 0; i < 4; ++i) d[j][i] = 0.f;

    run_mainloop(As3, Bs3, m_base, n_base, g, tig, d);
    __syncthreads();

    float* Cs = smem_dyn;   // reuse whole region for C staging
#pragma unroll
    for (int j = 0; j < 8; ++j) {
        int c = n_base + j * 8 + 2 * tig;
        *(float2*)(Cs + (m_base + g) * CS_STRIDE + c)     = make_float2(d[j][0], d[j][1]);
        *(float2*)(Cs + (m_base + g + 8) * CS_STRIDE + c) = make_float2(d[j][2], d[j][3]);
    }
    __syncthreads();

    // Epilogue: msg = relu(Cs + P[s] + Q[r]); red.v4 scatter into out[r]
    const int eg = tid >> 5;
    const int og = tid & 31;
#pragma unroll
    for (int i = 0; i < 8; ++i) {
        int el = eg * 8 + i;
        int e  = e0 + el;
        int s  = senders[e];
        int r  = receivers[e];
        float4 m = *(const float4*)(Cs + el * CS_STRIDE + og * 4);
        uint2 pu = *(const uint2*)(g_PQh + (size_t)s * 128 + og * 2);
        uint2 qu = *(const uint2*)(g_PQh + (size_t)r * 128 + 64 + og * 2);
        float2 p0 = h2f2(pu.x), p1 = h2f2(pu.y);
        float2 q0 = h2f2(qu.x), q1 = h2f2(qu.y);
        m.x = fmaxf(m.x + p0.x + q0.x, 0.f);
        m.y = fmaxf(m.y + p0.y + q0.y, 0.f);
        m.z = fmaxf(m.z + p1.x + q1.x, 0.f);
        m.w = fmaxf(m.w + p1.y + q1.y, 0.f);
        float* dst = out + (size_t)r * H + og * 4;
        asm volatile("red.global.add.v4.f32 [%0], {%1,%2,%3,%4};"
                     :: "l"(dst), "f"(m.x), "f"(m.y), "f"(m.z), "f"(m.w)
                     : "memory");
    }
}

// ---------------------------------------------------------------------------
// Kernel 3: in-place LayerNorm, one warp per row
// ---------------------------------------------------------------------------
__global__ __launch_bounds__(256) void ln_kernel(float* __restrict__ out,
                                                 const float* __restrict__ gamma,
                                                 const float* __restrict__ beta) {
    int warp = threadIdx.x >> 5;
    int lane = threadIdx.x & 31;
    int row  = blockIdx.x * 8 + warp;
    if (row >= N_NODES) return;

    float4 h = *(const float4*)(out + (size_t)row * H + lane * 4);
    float s  = h.x + h.y + h.z + h.w;
    float s2 = h.x * h.x + h.y * h.y + h.z * h.z + h.w * h.w;
#pragma unroll
    for (int off = 16; off > 0; off >>= 1) {
        s  += __shfl_xor_sync(0xffffffffu, s, off);
        s2 += __shfl_xor_sync(0xffffffffu, s2, off);
    }
    float mean = s * (1.f / H);
    float var  = s2 * (1.f / H) - mean * mean;
    float rstd = rsqrtf(var + LN_EPS);

    float4 g = *(const float4*)(gamma + lane * 4);
    float4 b = *(const float4*)(beta + lane * 4);
    float4 o;
    o.x = g.x * (h.x - mean) * rstd + b.x;
    o.y = g.y * (h.y - mean) * rstd + b.y;
    o.z = g.z * (h.z - mean) * rstd + b.z;
    o.w = g.w * (h.w - mean) * rstd + b.w;
    *(float4*)(out + (size_t)row * H + lane * 4) = o;
}

// ---------------------------------------------------------------------------
extern "C" void kernel_launch(void* const* d_in, const int* in_sizes, int n_in,
                              void* d_out, int out_size) {
    const float* x         = (const float*)d_in[0];
    const int*   senders   = (const int*)d_in[1];
    const int*   receivers = (const int*)d_in[2];
    const float* ef        = (const float*)d_in[3];
    const float* W1        = (const float*)d_in[4];
    const float* b1        = (const float*)d_in[5];
    const float* gamma     = (const float*)d_in[6];
    const float* beta      = (const float*)d_in[7];
    float*       out       = (float*)d_out;

    cudaFuncSetAttribute(edge_kernel, cudaFuncAttributeMaxDynamicSharedMemorySize,
                         SMEM_TILE);
    cudaFuncSetAttribute(proj_kernel, cudaFuncAttributeMaxDynamicSharedMemorySize,
                         SMEM_TILE);

    pack_w_kernel<<<1, 256>>>(W1);
    proj_kernel<<<dim3((N_NODES + 63) / 64, 2), 256, SMEM_TILE>>>(x, b1, out);
    edge_kernel<<<N_EDGES / 64, 256, SMEM_TILE>>>(ef, senders, receivers, out);
    ln_kernel<<<N_NODES / 8, 256>>>(out, gamma, beta);
}

// round 15
// speedup vs baseline: 1.4273x; 1.0425x over previous
#include <cuda_runtime.h>
#include <cuda_fp16.h>
#include <math.h>
#include <stdint.h>

#define N_NODES 50000
#define N_EDGES 800000
#define H 128
#define LN_EPS 1e-5f

// k-paired layouts: element = uint2 { f16x2(k-pair kp) , f16x2(k-pair kp+4) }
// A: 64 rows x 32 pairs, stride 36 uint2 (conflict-free LDS.64)
// B: 32 pair-rows x 128 cols, stride 132 uint2 (conflict-free LDS.64)
#define AS3_STRIDE 36    // uint2 units per A row (32 data + 4 pad)
#define BS3_STRIDE 132   // uint2 units per B pair-row (128 data + 4 pad)
#define CS_STRIDE  132   // float units per C row in epilogue staging (fits B region)
#define SMEM_A3 (64 * AS3_STRIDE * 8)            // 18432 B
#define SMEM_B3 (32 * BS3_STRIDE * 8)            // 33792 B
#define SMEM_PROJ (SMEM_A3 + SMEM_B3)            // 52224 B
#define SMEM_SR   512                            // 64 senders + 64 receivers ints
#define SMEM_EDGE (SMEM_A3 + SMEM_B3 + SMEM_SR)  // 52736 B (4 CTA/SM)

// Static device scratch
// g_PQh: per-node projections, fp16 half2 pairs. [node][128] uint32:
//   0..63 = P = x@Ws + b1, 64..127 = Q = x@Wr
__device__ uint32_t g_PQh[(size_t)N_NODES * 128];
// g_Wh: W1 pre-packed fp16 k-PAIRED tiles: [3][32*BS3_STRIDE] uint2 (Ws|Wr|We)
__device__ uint2 g_Wh[3 * 32 * BS3_STRIDE];

// Pack two floats into f16x2: lo half = a, hi half = b.
__device__ __forceinline__ uint32_t pack_h2(float a, float b) {
    uint32_t u;
    asm("cvt.rn.f16x2.f32 %0, %1, %2;" : "=r"(u) : "f"(b), "f"(a));
    return u;
}

__device__ __forceinline__ float2 h2f2(uint32_t u) {
    __half2 h = *(__half2*)&u;
    return __half22float2(h);
}

__device__ __forceinline__ uint32_t smem_u32(const void* p) {
    uint32_t a;
    asm("{ .reg .u64 t; cvta.to.shared.u64 t, %1; cvt.u32.u64 %0, t; }" : "=r"(a) : "l"(p));
    return a;
}

__device__ __forceinline__ void cp_async16(uint32_t dst_smem, const void* src) {
    asm volatile("cp.async.cg.shared.global [%0], [%1], 16;"
                 :: "r"(dst_smem), "l"(src) : "memory");
}

__device__ __forceinline__ void cp_async_commit_wait() {
    asm volatile("cp.async.commit_group;" ::: "memory");
    asm volatile("cp.async.wait_group 0;" ::: "memory");
}

__device__ __forceinline__ void mma_f16(float d[4], uint32_t a0, uint32_t a1,
                                        uint32_t a2, uint32_t a3,
                                        uint32_t b0, uint32_t b1) {
    asm volatile(
        "mma.sync.aligned.m16n8k16.row.col.f32.f16.f16.f32 "
        "{%0,%1,%2,%3}, {%4,%5,%6,%7}, {%8,%9}, {%0,%1,%2,%3};"
        : "+f"(d[0]), "+f"(d[1]), "+f"(d[2]), "+f"(d[3])
        : "r"(a0), "r"(a1), "r"(a2), "r"(a3), "r"(b0), "r"(b1));
}

// ---------------------------------------------------------------------------
// Kernel 0: pack W1 sections into fp16 k-PAIRED layout.
// pair-row pr <-> (kp, kp+4) with kp = (pr>>2)*8 + (pr&3).
// Bs3[pr][n] = { h2(W[2kp][n],W[2kp+1][n]), h2(W[2kp+8][n],W[2kp+9][n]) }
// ---------------------------------------------------------------------------
__global__ __launch_bounds__(256) void pack_w_kernel(const float* __restrict__ W1) {
    const int tid = threadIdx.x;
    for (int sec = 0; sec < 3; ++sec) {
        const float* B = W1 + (size_t)sec * 128 * H;
        uint2* W = g_Wh + sec * 32 * BS3_STRIDE;
#pragma unroll
        for (int it = 0; it < 4; ++it) {
            int idx = tid + it * 256;        // 0..1023
            int pr  = idx >> 5;              // 0..31
            int ng  = idx & 31;              // n = 4*ng..+3
            int kp  = ((pr >> 2) << 3) + (pr & 3);
            float4 v0 = *(const float4*)(B + (size_t)(2 * kp)     * H + ng * 4);
            float4 v1 = *(const float4*)(B + (size_t)(2 * kp + 1) * H + ng * 4);
            float4 v2 = *(const float4*)(B + (size_t)(2 * kp + 8) * H + ng * 4);
            float4 v3 = *(const float4*)(B + (size_t)(2 * kp + 9) * H + ng * 4);
            uint2* dst = W + pr * BS3_STRIDE + ng * 4;
            dst[0] = make_uint2(pack_h2(v0.x, v1.x), pack_h2(v2.x, v3.x));
            dst[1] = make_uint2(pack_h2(v0.y, v1.y), pack_h2(v2.y, v3.y));
            dst[2] = make_uint2(pack_h2(v0.z, v1.z), pack_h2(v2.z, v3.z));
            dst[3] = make_uint2(pack_h2(v0.w, v1.w), pack_h2(v2.w, v3.w));
        }
    }
}

// ---------------------------------------------------------------------------
// Shared mainloop: A (paired) x B (paired) -> d[8][4], LDS.64 fragments
// ---------------------------------------------------------------------------
__device__ __forceinline__ void run_mainloop(const uint2* __restrict__ As3,
                                             const uint2* __restrict__ Bs3,
                                             int m_base, int n_base, int g, int tig,
                                             float d[8][4]) {
#pragma unroll
    for (int ks = 0; ks < 8; ++ks) {
        const uint2* ar = As3 + (m_base + g) * AS3_STRIDE + ks * 4 + tig;
        uint2 alo = ar[0];                    // {row g:   kp0+tig, kp0+tig+4}
        uint2 ahi = ar[8 * AS3_STRIDE];       // {row g+8: same pair}
        const uint2* br = Bs3 + (ks * 4 + tig) * BS3_STRIDE + n_base + g;
#pragma unroll
        for (int j = 0; j < 8; ++j) {
            uint2 b = br[j * 8];              // {row kp0+tig, row kp0+tig+4}
            mma_f16(d[j], alo.x, ahi.x, alo.y, ahi.y, b.x, b.y);
        }
    }
}

// ---------------------------------------------------------------------------
// Kernel 1: node projection, BOTH halves fused (A loaded once).
// sec 0: P = x@Ws + b1 (and out = x residual preload); sec 1: Q = x@Wr.
// C staging lives in the B region so the A tile survives across sections.
// ---------------------------------------------------------------------------
__global__ __launch_bounds__(256) void proj_kernel(const float* __restrict__ x,
                                                   const float* __restrict__ b1,
                                                   float* __restrict__ out) {
    extern __shared__ float smem_dyn[];
    uint2* As3 = (uint2*)smem_dyn;
    uint2* Bs3 = (uint2*)smem_dyn + 64 * AS3_STRIDE;
    float* CsB = (float*)Bs3;                // C staging overlays B region only

    const int tid = threadIdx.x;
    const int m0  = blockIdx.x * 64;

    // Kick off B (sec 0) async copy
    {
        const uint2* W = g_Wh + 0 * 32 * BS3_STRIDE;
#pragma unroll
        for (int it = 0; it < 8; ++it) {
            int idx = tid + it * 256;
            int pr  = idx >> 6;
            int n2  = idx & 63;
            cp_async16(smem_u32(Bs3 + pr * BS3_STRIDE + n2 * 2),
                       W + pr * BS3_STRIDE + n2 * 2);
        }
    }

    // A tile: x rows -> paired fp16 + out = x preload (once)
#pragma unroll
    for (int it = 0; it < 4; ++it) {
        int idx = tid + it * 256;
        int m   = idx >> 4;
        int r   = idx & 15;
        int ks  = r >> 1;
        int c   = r & 1;
        int n   = m0 + m;
        float4 vlo = make_float4(0.f, 0.f, 0.f, 0.f);
        float4 vhi = vlo;
        if (n < N_NODES) {
            const float* src = x + (size_t)n * H + (4 * ks + c) * 4;
            vlo = *(const float4*)(src);
            vhi = *(const float4*)(src + 8);
            float* o = out + (size_t)n * H + (4 * ks + c) * 4;
            *(float4*)(o)     = vlo;
            *(float4*)(o + 8) = vhi;
        }
        uint2* dst = As3 + m * AS3_STRIDE + 4 * ks + 2 * c;
        dst[0] = make_uint2(pack_h2(vlo.x, vlo.y), pack_h2(vhi.x, vhi.y));
        dst[1] = make_uint2(pack_h2(vlo.z, vlo.w), pack_h2(vhi.z, vhi.w));
    }
    cp_async_commit_wait();
    __syncthreads();

    const int lane = tid & 31;
    const int wid  = tid >> 5;
    const int g    = lane >> 2;
    const int tig  = lane & 3;
    const int m_base = (wid & 3) * 16;
    const int n_base = (wid >> 2) * 64;
    const int eg = tid >> 5;
    const int og = tid & 31;

    for (int sec = 0; sec < 2; ++sec) {
        float d[8][4];
#pragma unroll
        for (int j = 0; j < 8; ++j)
#pragma unroll
            for (int i = 0; i < 4; ++i) d[j][i] = 0.f;

        run_mainloop(As3, Bs3, m_base, n_base, g, tig, d);
        __syncthreads();   // all warps done reading B before staging C over it

        // Stage C into the B region (A untouched)
#pragma unroll
        for (int j = 0; j < 8; ++j) {
            int c = n_base + j * 8 + 2 * tig;
            *(float2*)(CsB + (m_base + g) * CS_STRIDE + c)     = make_float2(d[j][0], d[j][1]);
            *(float2*)(CsB + (m_base + g + 8) * CS_STRIDE + c) = make_float2(d[j][2], d[j][3]);
        }
        __syncthreads();

        // Epilogue: add bias (sec 0), pack fp16, store to g_PQh
        float4 bias = make_float4(0.f, 0.f, 0.f, 0.f);
        if (sec == 0) bias = *(const float4*)(b1 + og * 4);

#pragma unroll
        for (int i = 0; i < 8; ++i) {
            int el = eg * 8 + i;
            int n  = m0 + el;
            if (n < N_NODES) {
                float4 v = *(const float4*)(CsB + el * CS_STRIDE + og * 4);
                v.x += bias.x; v.y += bias.y; v.z += bias.z; v.w += bias.w;
                uint2 u;
                u.x = pack_h2(v.x, v.y);
                u.y = pack_h2(v.z, v.w);
                *(uint2*)(g_PQh + (size_t)n * 128 + sec * 64 + og * 2) = u;
            }
        }

        if (sec == 0) {
            __syncthreads();   // everyone done reading Cs before B1 overwrites
            const uint2* W = g_Wh + 1 * 32 * BS3_STRIDE;
#pragma unroll
            for (int it = 0; it < 8; ++it) {
                int idx = tid + it * 256;
                int pr  = idx >> 6;
                int n2  = idx & 63;
                cp_async16(smem_u32(Bs3 + pr * BS3_STRIDE + n2 * 2),
                           W + pr * BS3_STRIDE + n2 * 2);
            }
            cp_async_commit_wait();
            __syncthreads();
        }
    }
}

// ---------------------------------------------------------------------------
// Kernel 2: edge GEMM (R14 structure; B tile + (s,r) indices via cp.async).
// ---------------------------------------------------------------------------
__global__ __launch_bounds__(256) void edge_kernel(const float* __restrict__ ef,
                                                   const int* __restrict__ senders,
                                                   const int* __restrict__ receivers,
                                                   float* __restrict__ out) {
    extern __shared__ float smem_dyn[];
    uint2* As3 = (uint2*)smem_dyn;
    uint2* Bs3 = (uint2*)smem_dyn + 64 * AS3_STRIDE;
    int*   SRs = (int*)((char*)smem_dyn + SMEM_PROJ);   // [64] senders | [64] receivers

    const int tid = threadIdx.x;
    const int e0  = blockIdx.x * 64;

    // Async: B tile (32 KB) + the 64 (s,r) index pairs (512 B)
    const uint2* W = g_Wh + 2 * 32 * BS3_STRIDE;
#pragma unroll
    for (int it = 0; it < 8; ++it) {
        int idx = tid + it * 256;
        int pr  = idx >> 6;
        int n2  = idx & 63;
        cp_async16(smem_u32(Bs3 + pr * BS3_STRIDE + n2 * 2),
                   W + pr * BS3_STRIDE + n2 * 2);
    }
    if (tid < 16) {
        cp_async16(smem_u32(SRs + tid * 4), senders + e0 + tid * 4);
    } else if (tid < 32) {
        int t = tid - 16;
        cp_async16(smem_u32(SRs + 64 + t * 4), receivers + e0 + t * 4);
    }

    // A tile: edge_feat rows -> paired fp16 (overlaps the async copies)
#pragma unroll
    for (int it = 0; it < 4; ++it) {
        int idx = tid + it * 256;
        int e   = idx >> 4;
        int r   = idx & 15;
        int ks  = r >> 1;
        int c   = r & 1;
        const float* src = ef + (size_t)(e0 + e) * H + (4 * ks + c) * 4;
        float4 vlo = *(const float4*)(src);
        float4 vhi = *(const float4*)(src + 8);
        uint2* dst = As3 + e * AS3_STRIDE + 4 * ks + 2 * c;
        dst[0] = make_uint2(pack_h2(vlo.x, vlo.y), pack_h2(vhi.x, vhi.y));
        dst[1] = make_uint2(pack_h2(vlo.z, vlo.w), pack_h2(vhi.z, vhi.w));
    }
    cp_async_commit_wait();
    __syncthreads();

    const int lane = tid & 31;
    const int wid  = tid >> 5;
    const int g    = lane >> 2;
    const int tig  = lane & 3;
    const int m_base = (wid & 3) * 16;
    const int n_base = (wid >> 2) * 64;

    float d[8][4];
#pragma unroll
    for (int j = 0; j < 8; ++j)
#pragma unroll
        for (int i = 0; i < 4; ++i) d[j][i] = 0.f;

    run_mainloop(As3, Bs3, m_base, n_base, g, tig, d);
    __syncthreads();

    float* Cs = smem_dyn;   // reuse A+B region for C staging (SRs untouched above it)
#pragma unroll
    for (int j = 0; j < 8; ++j) {
        int c = n_base + j * 8 + 2 * tig;
        *(float2*)(Cs + (m_base + g) * CS_STRIDE + c)     = make_float2(d[j][0], d[j][1]);
        *(float2*)(Cs + (m_base + g + 8) * CS_STRIDE + c) = make_float2(d[j][2], d[j][3]);
    }
    __syncthreads();

    // Epilogue: msg = relu(Cs + P[s] + Q[r]); red.v4 scatter into out[r]
    const int eg = tid >> 5;
    const int og = tid & 31;
#pragma unroll
    for (int i = 0; i < 8; ++i) {
        int el = eg * 8 + i;
        int s  = SRs[el];
        int r  = SRs[64 + el];
        float4 m = *(const float4*)(Cs + el * CS_STRIDE + og * 4);
        uint2 pu = *(const uint2*)(g_PQh + (size_t)s * 128 + og * 2);
        uint2 qu = *(const uint2*)(g_PQh + (size_t)r * 128 + 64 + og * 2);
        float2 p0 = h2f2(pu.x), p1 = h2f2(pu.y);
        float2 q0 = h2f2(qu.x), q1 = h2f2(qu.y);
        m.x = fmaxf(m.x + p0.x + q0.x, 0.f);
        m.y = fmaxf(m.y + p0.y + q0.y, 0.f);
        m.z = fmaxf(m.z + p1.x + q1.x, 0.f);
        m.w = fmaxf(m.w + p1.y + q1.y, 0.f);
        float* dst = out + (size_t)r * H + og * 4;
        asm volatile("red.global.add.v4.f32 [%0], {%1,%2,%3,%4};"
                     :: "l"(dst), "f"(m.x), "f"(m.y), "f"(m.z), "f"(m.w)
                     : "memory");
    }
}

// ---------------------------------------------------------------------------
// Kernel 3: in-place LayerNorm, one warp per row
// ---------------------------------------------------------------------------
__global__ __launch_bounds__(256) void ln_kernel(float* __restrict__ out,
                                                 const float* __restrict__ gamma,
                                                 const float* __restrict__ beta) {
    int warp = threadIdx.x >> 5;
    int lane = threadIdx.x & 31;
    int row  = blockIdx.x * 8 + warp;
    if (row >= N_NODES) return;

    float4 h = *(const float4*)(out + (size_t)row * H + lane * 4);
    float s  = h.x + h.y + h.z + h.w;
    float s2 = h.x * h.x + h.y * h.y + h.z * h.z + h.w * h.w;
#pragma unroll
    for (int off = 16; off > 0; off >>= 1) {
        s  += __shfl_xor_sync(0xffffffffu, s, off);
        s2 += __shfl_xor_sync(0xffffffffu, s2, off);
    }
    float mean = s * (1.f / H);
    float var  = s2 * (1.f / H) - mean * mean;
    float rstd = rsqrtf(var + LN_EPS);

    float4 g = *(const float4*)(gamma + lane * 4);
    float4 b = *(const float4*)(beta + lane * 4);
    float4 o;
    o.x = g.x * (h.x - mean) * rstd + b.x;
    o.y = g.y * (h.y - mean) * rstd + b.y;
    o.z = g.z * (h.z - mean) * rstd + b.z;
    o.w = g.w * (h.w - mean) * rstd + b.w;
    *(float4*)(out + (size_t)row * H + lane * 4) = o;
}

// ---------------------------------------------------------------------------
extern "C" void kernel_launch(void* const* d_in, const int* in_sizes, int n_in,
                              void* d_out, int out_size) {
    const float* x         = (const float*)d_in[0];
    const int*   senders   = (const int*)d_in[1];
    const int*   receivers = (const int*)d_in[2];
    const float* ef        = (const float*)d_in[3];
    const float* W1        = (const float*)d_in[4];
    const float* b1        = (const float*)d_in[5];
    const float* gamma     = (const float*)d_in[6];
    const float* beta      = (const float*)d_in[7];
    float*       out       = (float*)d_out;

    cudaFuncSetAttribute(edge_kernel, cudaFuncAttributeMaxDynamicSharedMemorySize,
                         SMEM_EDGE);
    cudaFuncSetAttribute(proj_kernel, cudaFuncAttributeMaxDynamicSharedMemorySize,
                         SMEM_PROJ);

    pack_w_kernel<<<1, 256>>>(W1);
    proj_kernel<<<(N_NODES + 63) / 64, 256, SMEM_PROJ>>>(x, b1, out);
    edge_kernel<<<N_EDGES / 64, 256, SMEM_EDGE>>>(ef, senders, receivers, out);
    ln_kernel<<<N_NODES / 8, 256>>>(out, gamma, beta);
}

// round 16
// speedup vs baseline: 1.5122x; 1.0595x over previous
#include <cuda_runtime.h>
#include <cuda_fp16.h>
#include <math.h>
#include <stdint.h>

#define N_NODES 50000
#define N_EDGES 800000
#define H 128
#define LN_EPS 1e-5f

// k-paired layouts: element = uint2 { f16x2(k-pair kp) , f16x2(k-pair kp+4) }
// A: 64 rows x 32 pairs, stride 36 uint2 (conflict-free LDS.64)
// B: 32 pair-rows x 128 cols, stride 132 uint2 (conflict-free LDS.64)
#define AS3_STRIDE 36    // uint2 units per A row (32 data + 4 pad)
#define BS3_STRIDE 132   // uint2 units per B pair-row (128 data + 4 pad)
#define CS_STRIDE  132   // float units per C row in epilogue staging
#define SMEM_A3 (64 * AS3_STRIDE * 8)            // 18432 B
#define SMEM_B3 (32 * BS3_STRIDE * 8)            // 33792 B
#define SMEM_PROJ (SMEM_A3 + SMEM_B3)            // 52224 B
#define SMEM_SR   512                            // 64 senders + 64 receivers ints
#define SMEM_EDGE (SMEM_A3 + SMEM_B3 + SMEM_SR)  // 52736 B (4 CTA/SM)

// Static device scratch
// g_PQh: per-node projections, fp16 half2 pairs. [node][128] uint32:
//   0..63 = P = x@Ws + b1, 64..127 = Q = x@Wr
__device__ uint32_t g_PQh[(size_t)N_NODES * 128];
// g_Wh: W1 pre-packed fp16 k-PAIRED tiles: [3][32*BS3_STRIDE] uint2 (Ws|Wr|We)
__device__ uint2 g_Wh[3 * 32 * BS3_STRIDE];

// Pack two floats into f16x2: lo half = a, hi half = b.
__device__ __forceinline__ uint32_t pack_h2(float a, float b) {
    uint32_t u;
    asm("cvt.rn.f16x2.f32 %0, %1, %2;" : "=r"(u) : "f"(b), "f"(a));
    return u;
}

__device__ __forceinline__ float2 h2f2(uint32_t u) {
    __half2 h = *(__half2*)&u;
    return __half22float2(h);
}

__device__ __forceinline__ uint32_t smem_u32(const void* p) {
    uint32_t a;
    asm("{ .reg .u64 t; cvta.to.shared.u64 t, %1; cvt.u32.u64 %0, t; }" : "=r"(a) : "l"(p));
    return a;
}

__device__ __forceinline__ void cp_async16(uint32_t dst_smem, const void* src) {
    asm volatile("cp.async.cg.shared.global [%0], [%1], 16;"
                 :: "r"(dst_smem), "l"(src) : "memory");
}

__device__ __forceinline__ void cp_async_commit_wait() {
    asm volatile("cp.async.commit_group;" ::: "memory");
    asm volatile("cp.async.wait_group 0;" ::: "memory");
}

__device__ __forceinline__ void mma_f16(float d[4], uint32_t a0, uint32_t a1,
                                        uint32_t a2, uint32_t a3,
                                        uint32_t b0, uint32_t b1) {
    asm volatile(
        "mma.sync.aligned.m16n8k16.row.col.f32.f16.f16.f32 "
        "{%0,%1,%2,%3}, {%4,%5,%6,%7}, {%8,%9}, {%0,%1,%2,%3};"
        : "+f"(d[0]), "+f"(d[1]), "+f"(d[2]), "+f"(d[3])
        : "r"(a0), "r"(a1), "r"(a2), "r"(a3), "r"(b0), "r"(b1));
}

// ---------------------------------------------------------------------------
// Kernel 0: pack W1 sections into fp16 k-PAIRED layout.
// pair-row pr <-> (kp, kp+4) with kp = (pr>>2)*8 + (pr&3).
// Bs3[pr][n] = { h2(W[2kp][n],W[2kp+1][n]), h2(W[2kp+8][n],W[2kp+9][n]) }
// ---------------------------------------------------------------------------
__global__ __launch_bounds__(256) void pack_w_kernel(const float* __restrict__ W1) {
    const int tid = threadIdx.x;
    for (int sec = 0; sec < 3; ++sec) {
        const float* B = W1 + (size_t)sec * 128 * H;
        uint2* W = g_Wh + sec * 32 * BS3_STRIDE;
#pragma unroll
        for (int it = 0; it < 4; ++it) {
            int idx = tid + it * 256;        // 0..1023
            int pr  = idx >> 5;              // 0..31
            int ng  = idx & 31;              // n = 4*ng..+3
            int kp  = ((pr >> 2) << 3) + (pr & 3);
            float4 v0 = *(const float4*)(B + (size_t)(2 * kp)     * H + ng * 4);
            float4 v1 = *(const float4*)(B + (size_t)(2 * kp + 1) * H + ng * 4);
            float4 v2 = *(const float4*)(B + (size_t)(2 * kp + 8) * H + ng * 4);
            float4 v3 = *(const float4*)(B + (size_t)(2 * kp + 9) * H + ng * 4);
            uint2* dst = W + pr * BS3_STRIDE + ng * 4;
            dst[0] = make_uint2(pack_h2(v0.x, v1.x), pack_h2(v2.x, v3.x));
            dst[1] = make_uint2(pack_h2(v0.y, v1.y), pack_h2(v2.y, v3.y));
            dst[2] = make_uint2(pack_h2(v0.z, v1.z), pack_h2(v2.z, v3.z));
            dst[3] = make_uint2(pack_h2(v0.w, v1.w), pack_h2(v2.w, v3.w));
        }
    }
}

// ---------------------------------------------------------------------------
// Shared mainloop: A (paired) x B (paired) -> d[8][4], LDS.64 fragments
// ---------------------------------------------------------------------------
__device__ __forceinline__ void run_mainloop(const uint2* __restrict__ As3,
                                             const uint2* __restrict__ Bs3,
                                             int m_base, int n_base, int g, int tig,
                                             float d[8][4]) {
#pragma unroll
    for (int ks = 0; ks < 8; ++ks) {
        const uint2* ar = As3 + (m_base + g) * AS3_STRIDE + ks * 4 + tig;
        uint2 alo = ar[0];                    // {row g:   kp0+tig, kp0+tig+4}
        uint2 ahi = ar[8 * AS3_STRIDE];       // {row g+8: same pair}
        const uint2* br = Bs3 + (ks * 4 + tig) * BS3_STRIDE + n_base + g;
#pragma unroll
        for (int j = 0; j < 8; ++j) {
            uint2 b = br[j * 8];              // {row kp0+tig, row kp0+tig+4}
            mma_f16(d[j], alo.x, ahi.x, alo.y, ahi.y, b.x, b.y);
        }
    }
}

// ---------------------------------------------------------------------------
// Kernel 1: node projection, BOTH halves fused (A loaded once).
// sec 0: P = x@Ws + b1 (and out = x residual preload); sec 1: Q = x@Wr.
// C staging lives in the B region so the A tile survives across sections.
// ---------------------------------------------------------------------------
__global__ __launch_bounds__(256) void proj_kernel(const float* __restrict__ x,
                                                   const float* __restrict__ b1,
                                                   float* __restrict__ out) {
    extern __shared__ float smem_dyn[];
    uint2* As3 = (uint2*)smem_dyn;
    uint2* Bs3 = (uint2*)smem_dyn + 64 * AS3_STRIDE;
    float* CsB = (float*)Bs3;                // C staging overlays B region only

    const int tid = threadIdx.x;
    const int m0  = blockIdx.x * 64;

    // Kick off B (sec 0) async copy
    {
        const uint2* W = g_Wh + 0 * 32 * BS3_STRIDE;
#pragma unroll
        for (int it = 0; it < 8; ++it) {
            int idx = tid + it * 256;
            int pr  = idx >> 6;
            int n2  = idx & 63;
            cp_async16(smem_u32(Bs3 + pr * BS3_STRIDE + n2 * 2),
                       W + pr * BS3_STRIDE + n2 * 2);
        }
    }

    // A tile: x rows -> paired fp16 + out = x preload (once)
#pragma unroll
    for (int it = 0; it < 4; ++it) {
        int idx = tid + it * 256;
        int m   = idx >> 4;
        int r   = idx & 15;
        int ks  = r >> 1;
        int c   = r & 1;
        int n   = m0 + m;
        float4 vlo = make_float4(0.f, 0.f, 0.f, 0.f);
        float4 vhi = vlo;
        if (n < N_NODES) {
            const float* src = x + (size_t)n * H + (4 * ks + c) * 4;
            vlo = *(const float4*)(src);
            vhi = *(const float4*)(src + 8);
            float* o = out + (size_t)n * H + (4 * ks + c) * 4;
            *(float4*)(o)     = vlo;
            *(float4*)(o + 8) = vhi;
        }
        uint2* dst = As3 + m * AS3_STRIDE + 4 * ks + 2 * c;
        dst[0] = make_uint2(pack_h2(vlo.x, vlo.y), pack_h2(vhi.x, vhi.y));
        dst[1] = make_uint2(pack_h2(vlo.z, vlo.w), pack_h2(vhi.z, vhi.w));
    }
    cp_async_commit_wait();
    __syncthreads();

    const int lane = tid & 31;
    const int wid  = tid >> 5;
    const int g    = lane >> 2;
    const int tig  = lane & 3;
    const int m_base = (wid & 3) * 16;
    const int n_base = (wid >> 2) * 64;
    const int eg = tid >> 5;
    const int og = tid & 31;

    for (int sec = 0; sec < 2; ++sec) {
        float d[8][4];
#pragma unroll
        for (int j = 0; j < 8; ++j)
#pragma unroll
            for (int i = 0; i < 4; ++i) d[j][i] = 0.f;

        run_mainloop(As3, Bs3, m_base, n_base, g, tig, d);
        __syncthreads();   // all warps done reading B before staging C over it

        // Stage C into the B region (A untouched)
#pragma unroll
        for (int j = 0; j < 8; ++j) {
            int c = n_base + j * 8 + 2 * tig;
            *(float2*)(CsB + (m_base + g) * CS_STRIDE + c)     = make_float2(d[j][0], d[j][1]);
            *(float2*)(CsB + (m_base + g + 8) * CS_STRIDE + c) = make_float2(d[j][2], d[j][3]);
        }
        __syncthreads();

        // Epilogue: add bias (sec 0), pack fp16, store to g_PQh
        float4 bias = make_float4(0.f, 0.f, 0.f, 0.f);
        if (sec == 0) bias = *(const float4*)(b1 + og * 4);

#pragma unroll
        for (int i = 0; i < 8; ++i) {
            int el = eg * 8 + i;
            int n  = m0 + el;
            if (n < N_NODES) {
                float4 v = *(const float4*)(CsB + el * CS_STRIDE + og * 4);
                v.x += bias.x; v.y += bias.y; v.z += bias.z; v.w += bias.w;
                uint2 u;
                u.x = pack_h2(v.x, v.y);
                u.y = pack_h2(v.z, v.w);
                *(uint2*)(g_PQh + (size_t)n * 128 + sec * 64 + og * 2) = u;
            }
        }

        if (sec == 0) {
            __syncthreads();   // everyone done reading Cs before B1 overwrites
            const uint2* W = g_Wh + 1 * 32 * BS3_STRIDE;
#pragma unroll
            for (int it = 0; it < 8; ++it) {
                int idx = tid + it * 256;
                int pr  = idx >> 6;
                int n2  = idx & 63;
                cp_async16(smem_u32(Bs3 + pr * BS3_STRIDE + n2 * 2),
                           W + pr * BS3_STRIDE + n2 * 2);
            }
            cp_async_commit_wait();
            __syncthreads();
        }
    }
}

// ---------------------------------------------------------------------------
// Kernel 2: edge GEMM (R15 structure; epilogue gathers batched 4-wide for MLP).
// ---------------------------------------------------------------------------
__global__ __launch_bounds__(256) void edge_kernel(const float* __restrict__ ef,
                                                   const int* __restrict__ senders,
                                                   const int* __restrict__ receivers,
                                                   float* __restrict__ out) {
    extern __shared__ float smem_dyn[];
    uint2* As3 = (uint2*)smem_dyn;
    uint2* Bs3 = (uint2*)smem_dyn + 64 * AS3_STRIDE;
    int*   SRs = (int*)((char*)smem_dyn + SMEM_PROJ);   // [64] senders | [64] receivers

    const int tid = threadIdx.x;
    const int e0  = blockIdx.x * 64;

    // Async: B tile (32 KB) + the 64 (s,r) index pairs (512 B)
    const uint2* W = g_Wh + 2 * 32 * BS3_STRIDE;
#pragma unroll
    for (int it = 0; it < 8; ++it) {
        int idx = tid + it * 256;
        int pr  = idx >> 6;
        int n2  = idx & 63;
        cp_async16(smem_u32(Bs3 + pr * BS3_STRIDE + n2 * 2),
                   W + pr * BS3_STRIDE + n2 * 2);
    }
    if (tid < 16) {
        cp_async16(smem_u32(SRs + tid * 4), senders + e0 + tid * 4);
    } else if (tid < 32) {
        int t = tid - 16;
        cp_async16(smem_u32(SRs + 64 + t * 4), receivers + e0 + t * 4);
    }

    // A tile: edge_feat rows -> paired fp16 (overlaps the async copies)
#pragma unroll
    for (int it = 0; it < 4; ++it) {
        int idx = tid + it * 256;
        int e   = idx >> 4;
        int r   = idx & 15;
        int ks  = r >> 1;
        int c   = r & 1;
        const float* src = ef + (size_t)(e0 + e) * H + (4 * ks + c) * 4;
        float4 vlo = *(const float4*)(src);
        float4 vhi = *(const float4*)(src + 8);
        uint2* dst = As3 + e * AS3_STRIDE + 4 * ks + 2 * c;
        dst[0] = make_uint2(pack_h2(vlo.x, vlo.y), pack_h2(vhi.x, vhi.y));
        dst[1] = make_uint2(pack_h2(vlo.z, vlo.w), pack_h2(vhi.z, vhi.w));
    }
    cp_async_commit_wait();
    __syncthreads();

    const int lane = tid & 31;
    const int wid  = tid >> 5;
    const int g    = lane >> 2;
    const int tig  = lane & 3;
    const int m_base = (wid & 3) * 16;
    const int n_base = (wid >> 2) * 64;

    float d[8][4];
#pragma unroll
    for (int j = 0; j < 8; ++j)
#pragma unroll
        for (int i = 0; i < 4; ++i) d[j][i] = 0.f;

    run_mainloop(As3, Bs3, m_base, n_base, g, tig, d);
    __syncthreads();

    float* Cs = smem_dyn;   // reuse A+B region for C staging (SRs untouched above it)
#pragma unroll
    for (int j = 0; j < 8; ++j) {
        int c = n_base + j * 8 + 2 * tig;
        *(float2*)(Cs + (m_base + g) * CS_STRIDE + c)     = make_float2(d[j][0], d[j][1]);
        *(float2*)(Cs + (m_base + g + 8) * CS_STRIDE + c) = make_float2(d[j][2], d[j][3]);
    }
    __syncthreads();

    // Epilogue in two batches of 4 edges: issue all gathers for the batch
    // back-to-back (MLP ~8), then compute + RED.
    const int eg = tid >> 5;
    const int og = tid & 31;
#pragma unroll
    for (int b = 0; b < 2; ++b) {
        int rr[4];
        uint2 pu[4], qu[4];
        float4 m[4];
#pragma unroll
        for (int i = 0; i < 4; ++i) {
            int el = eg * 8 + b * 4 + i;
            int s  = SRs[el];
            rr[i]  = SRs[64 + el];
            pu[i] = *(const uint2*)(g_PQh + (size_t)s * 128 + og * 2);
            qu[i] = *(const uint2*)(g_PQh + (size_t)rr[i] * 128 + 64 + og * 2);
            m[i]  = *(const float4*)(Cs + el * CS_STRIDE + og * 4);
        }
#pragma unroll
        for (int i = 0; i < 4; ++i) {
            float2 p0 = h2f2(pu[i].x), p1 = h2f2(pu[i].y);
            float2 q0 = h2f2(qu[i].x), q1 = h2f2(qu[i].y);
            float v0 = fmaxf(m[i].x + p0.x + q0.x, 0.f);
            float v1 = fmaxf(m[i].y + p0.y + q0.y, 0.f);
            float v2 = fmaxf(m[i].z + p1.x + q1.x, 0.f);
            float v3 = fmaxf(m[i].w + p1.y + q1.y, 0.f);
            float* dst = out + (size_t)rr[i] * H + og * 4;
            asm volatile("red.global.add.v4.f32 [%0], {%1,%2,%3,%4};"
                         :: "l"(dst), "f"(v0), "f"(v1), "f"(v2), "f"(v3)
                         : "memory");
        }
    }
}

// ---------------------------------------------------------------------------
// Kernel 3: in-place LayerNorm, one warp per row
// ---------------------------------------------------------------------------
__global__ __launch_bounds__(256) void ln_kernel(float* __restrict__ out,
                                                 const float* __restrict__ gamma,
                                                 const float* __restrict__ beta) {
    int warp = threadIdx.x >> 5;
    int lane = threadIdx.x & 31;
    int row  = blockIdx.x * 8 + warp;
    if (row >= N_NODES) return;

    float4 h = *(const float4*)(out + (size_t)row * H + lane * 4);
    float s  = h.x + h.y + h.z + h.w;
    float s2 = h.x * h.x + h.y * h.y + h.z * h.z + h.w * h.w;
#pragma unroll
    for (int off = 16; off > 0; off >>= 1) {
        s  += __shfl_xor_sync(0xffffffffu, s, off);
        s2 += __shfl_xor_sync(0xffffffffu, s2, off);
    }
    float mean = s * (1.f / H);
    float var  = s2 * (1.f / H) - mean * mean;
    float rstd = rsqrtf(var + LN_EPS);

    float4 g = *(const float4*)(gamma + lane * 4);
    float4 b = *(const float4*)(beta + lane * 4);
    float4 o;
    o.x = g.x * (h.x - mean) * rstd + b.x;
    o.y = g.y * (h.y - mean) * rstd + b.y;
    o.z = g.z * (h.z - mean) * rstd + b.z;
    o.w = g.w * (h.w - mean) * rstd + b.w;
    *(float4*)(out + (size_t)row * H + lane * 4) = o;
}

// ---------------------------------------------------------------------------
extern "C" void kernel_launch(void* const* d_in, const int* in_sizes, int n_in,
                              void* d_out, int out_size) {
    const float* x         = (const float*)d_in[0];
    const int*   senders   = (const int*)d_in[1];
    const int*   receivers = (const int*)d_in[2];
    const float* ef        = (const float*)d_in[3];
    const float* W1        = (const float*)d_in[4];
    const float* b1        = (const float*)d_in[5];
    const float* gamma     = (const float*)d_in[6];
    const float* beta      = (const float*)d_in[7];
    float*       out       = (float*)d_out;

    cudaFuncSetAttribute(edge_kernel, cudaFuncAttributeMaxDynamicSharedMemorySize,
                         SMEM_EDGE);
    cudaFuncSetAttribute(proj_kernel, cudaFuncAttributeMaxDynamicSharedMemorySize,
                         SMEM_PROJ);

    pack_w_kernel<<<1, 256>>>(W1);
    proj_kernel<<<(N_NODES + 63) / 64, 256, SMEM_PROJ>>>(x, b1, out);
    edge_kernel<<<N_EDGES / 64, 256, SMEM_EDGE>>>(ef, senders, receivers, out);
    ln_kernel<<<N_NODES / 8, 256>>>(out, gamma, beta);
}